// round 4
// baseline (speedup 1.0000x reference)
#include <cuda_runtime.h>
#include <math.h>

#define FULL_MASK 0xffffffffu
#define MAX_B 4096
#define DLEV 5

__device__ float g_row_total[MAX_B];
__device__ unsigned int g_block_count = 0;   // reset by last block -> graph-replay safe

#define UPD4(V, I, Q, BASE)                               \
    do {                                                  \
        if ((Q).x > (V)) { (V) = (Q).x; (I) = (BASE);     } \
        if ((Q).y > (V)) { (V) = (Q).y; (I) = (BASE) + 1; } \
        if ((Q).z > (V)) { (V) = (Q).z; (I) = (BASE) + 2; } \
        if ((Q).w > (V)) { (V) = (Q).w; (I) = (BASE) + 3; } \
    } while (0)

#define MRG(V, I, V2, I2)                                 \
    do {                                                  \
        if ((V2) > (V) || ((V2) == (V) && (I2) < (I))) {  \
            (V) = (V2); (I) = (I2);                       \
        }                                                 \
    } while (0)

// 256 threads = 8 warps = 4 rows/block, 2 warps per row
__global__ void __launch_bounds__(256)
hier_loss_fused_kernel(
    const float* __restrict__ y_pred,
    const float* __restrict__ y_true,
    const float* __restrict__ class_weights,
    const int*   __restrict__ path_ids,   // [C, D]
    const int*   __restrict__ path_len,   // [C]
    const int*   __restrict__ sib_start,  // [C, D]
    const int*   __restrict__ sib_size,   // [C, D]
    float* __restrict__ out,
    int B, int C)
{
    const int warp = threadIdx.x >> 5;
    const int lane = threadIdx.x & 31;
    const int pair = warp >> 1;            // 0..3 : row slot within block
    const int half = warp & 1;             // which half-warp of the row
    const int row  = blockIdx.x * 4 + pair;

    // per-row merge slots: [pair][half]
    __shared__ float s_pv[4][2], s_tv[4][2];
    __shared__ int   s_pi[4][2], s_ti[4][2];

    if (row < B) {
        const float* prow = y_pred + (size_t)row * C;
        const float* trow = y_true + (size_t)row * C;

        const int n4 = C >> 2;  // 682
        const float4* p4 = reinterpret_cast<const float4*>(prow);
        const float4* t4 = reinterpret_cast<const float4*>(trow);

        float pv0 = -INFINITY, pv1 = -INFINITY, pv2 = -INFINITY, pv3 = -INFINITY;
        float tv0 = -INFINITY, tv1 = -INFINITY, tv2 = -INFINITY, tv3 = -INFINITY;
        int   pi0 = 0, pi1 = 0, pi2 = 0, pi3 = 0;
        int   ti0 = 0, ti1 = 0, ti2 = 0, ti3 = 0;

        // this warp covers i = lane + 32*half + 64*k  (interleaved halves)
        int i = lane + (half << 5);
        // unroll x4: 8 independent 16B loads before any compare
        for (; i + 192 < n4; i += 256) {
            float4 a0 = p4[i];
            float4 a1 = p4[i + 64];
            float4 a2 = p4[i + 128];
            float4 a3 = p4[i + 192];
            float4 b0 = t4[i];
            float4 b1 = t4[i + 64];
            float4 b2 = t4[i + 128];
            float4 b3 = t4[i + 192];
            UPD4(pv0, pi0, a0,  i        << 2);
            UPD4(pv1, pi1, a1, (i + 64)  << 2);
            UPD4(pv2, pi2, a2, (i + 128) << 2);
            UPD4(pv3, pi3, a3, (i + 192) << 2);
            UPD4(tv0, ti0, b0,  i        << 2);
            UPD4(tv1, ti1, b1, (i + 64)  << 2);
            UPD4(tv2, ti2, b2, (i + 128) << 2);
            UPD4(tv3, ti3, b3, (i + 192) << 2);
        }
        for (; i < n4; i += 64) {
            float4 a = p4[i];
            float4 b = t4[i];
            UPD4(pv0, pi0, a, i << 2);
            UPD4(tv0, ti0, b, i << 2);
        }
        // scalar remainder (none for C=2728)
        for (int c = (n4 << 2) + lane + (half << 5); c < C; c += 64) {
            float a = prow[c];
            float b = trow[c];
            if (a > pv0) { pv0 = a; pi0 = c; }
            if (b > tv0) { tv0 = b; ti0 = c; }
        }

        MRG(pv0, pi0, pv1, pi1);
        MRG(pv2, pi2, pv3, pi3);
        MRG(pv0, pi0, pv2, pi2);
        MRG(tv0, ti0, tv1, ti1);
        MRG(tv2, ti2, tv3, ti3);
        MRG(tv0, ti0, tv2, ti2);

        #pragma unroll
        for (int off = 16; off > 0; off >>= 1) {
            float opv = __shfl_down_sync(FULL_MASK, pv0, off);
            int   opi = __shfl_down_sync(FULL_MASK, pi0, off);
            MRG(pv0, pi0, opv, opi);
            float otv = __shfl_down_sync(FULL_MASK, tv0, off);
            int   oti = __shfl_down_sync(FULL_MASK, ti0, off);
            MRG(tv0, ti0, otv, oti);
        }

        if (lane == 0) {
            s_pv[pair][half] = pv0; s_pi[pair][half] = pi0;
            s_tv[pair][half] = tv0; s_ti[pair][half] = ti0;
        }
    }
    __syncthreads();

    if (row < B && half == 0 && lane == 0) {
        float pv = s_pv[pair][0]; int pi = s_pi[pair][0];
        float tv = s_tv[pair][0]; int ti = s_ti[pair][0];
        MRG(pv, pi, s_pv[pair][1], s_pi[pair][1]);
        MRG(tv, ti, s_tv[pair][1], s_ti[pair][1]);

        const float* prow = y_pred + (size_t)row * C;
        const int pred_top = pi;
        const int true_top = ti;
        const int len_p = path_len[pred_top];
        const int len_t = path_len[true_top];
        const int lmin  = (len_p < len_t) ? len_p : len_t;

        float total = 0.0f;
        const int diff = (len_p > len_t) ? (len_p - len_t) : (len_t - len_p);

        if (diff != 0) {   // else total is exactly 0
            float local = 0.0f;
            #pragma unroll
            for (int l = 0; l < DLEV; l++) {
                if (l < lmin) {
                    const int start = sib_start[true_top * DLEV + l];
                    const int size  = sib_size [true_top * DLEV + l];
                    const int tid_l = path_ids [true_top * DLEV + l];

                    // lse of (y_pred * 0/1 mask): masked-out classes contribute exp(0)=1
                    float s = (float)(C - size);
                    for (int c = start; c < start + size; c++) {
                        s += expf(prow[c]);
                    }
                    const float lse = logf(s);
                    const float ce  = lse - prow[tid_l];
                    const float h   = (float)(len_t - l - 1);
                    local += expf(-0.5f * h) * ce;
                }
            }
            total = local * (1.5f * (float)diff) * class_weights[true_top];
        }
        g_row_total[row] = total;
    }

    // ---- grid-wide deterministic reduction: last block sums everything ----
    __shared__ bool s_is_last;
    __syncthreads();                          // row totals written before fence
    if (threadIdx.x == 0) {
        __threadfence();                      // release g_row_total grid-wide
        unsigned int done = atomicAdd(&g_block_count, 1u);
        s_is_last = (done == gridDim.x - 1);
    }
    __syncthreads();

    if (s_is_last) {
        __shared__ float s_sum[8];
        float sum = 0.0f;
        for (int idx = threadIdx.x; idx < B; idx += blockDim.x)
            sum += g_row_total[idx];          // hot in L2
        #pragma unroll
        for (int off = 16; off > 0; off >>= 1)
            sum += __shfl_down_sync(FULL_MASK, sum, off);
        if (lane == 0) s_sum[warp] = sum;
        __syncthreads();
        if (warp == 0) {
            float v = (lane < 8) ? s_sum[lane] : 0.0f;
            #pragma unroll
            for (int off = 4; off > 0; off >>= 1)
                v += __shfl_down_sync(FULL_MASK, v, off);
            if (lane == 0) {
                out[0] = v / (float)B;
                g_block_count = 0;            // reset for next graph replay
            }
        }
    }
}

extern "C" void kernel_launch(void* const* d_in, const int* in_sizes, int n_in,
                              void* d_out, int out_size)
{
    const float* y_pred        = (const float*)d_in[0];
    const float* y_true        = (const float*)d_in[1];
    const float* class_weights = (const float*)d_in[2];
    const int*   path_ids      = (const int*)  d_in[3];
    const int*   path_len      = (const int*)  d_in[4];
    const int*   sib_start     = (const int*)  d_in[5];
    const int*   sib_size      = (const int*)  d_in[6];

    const int C = in_sizes[2];            // 2728
    const int B = in_sizes[0] / C;        // 4096

    const int rows_per_block = 4;         // 2 warps per row, 8 warps/block
    const int blocks = (B + rows_per_block - 1) / rows_per_block;   // 1024

    hier_loss_fused_kernel<<<blocks, 256>>>(
        y_pred, y_true, class_weights, path_ids, path_len, sib_start, sib_size,
        (float*)d_out, B, C);
}

// round 5
// speedup vs baseline: 1.3050x; 1.3050x over previous
#include <cuda_runtime.h>
#include <math.h>

#define FULL_MASK 0xffffffffu
#define MAX_B 4096
#define DLEV 5

__device__ float g_row_total[MAX_B];

// merge two trackers, lowest index wins ties
#define MRG(V, I, V2, I2)                                 \
    do {                                                  \
        if ((V2) > (V) || ((V2) == (V) && (I2) < (I))) {  \
            (V) = (V2); (I) = (I2);                       \
        }                                                 \
    } while (0)

// 256 threads = 8 warps; warp w handles tensor (w&1) of row (blockIdx.x*4 + w/2).
// Minimal register footprint -> high occupancy.
__global__ void __launch_bounds__(256)
hier_loss_row_kernel(
    const float* __restrict__ y_pred,
    const float* __restrict__ y_true,
    const float* __restrict__ class_weights,
    const int*   __restrict__ path_ids,   // [C, D]
    const int*   __restrict__ path_len,   // [C]
    const int*   __restrict__ sib_start,  // [C, D]
    const int*   __restrict__ sib_size,   // [C, D]
    int B, int C)
{
    const int warp  = threadIdx.x >> 5;
    const int lane  = threadIdx.x & 31;
    const int slot  = warp >> 1;          // 0..3 row slot within block
    const int which = warp & 1;           // 0 = y_pred, 1 = y_true
    const int row   = blockIdx.x * 4 + slot;

    __shared__ float s_val[8];
    __shared__ int   s_idx[8];

    if (row < B) {
        const float* src = (which ? y_true : y_pred) + (size_t)row * C;
        const float4* s4 = reinterpret_cast<const float4*>(src);
        const int n4 = C >> 2;            // 682

        float v0 = -INFINITY, v1 = -INFINITY;
        int   i0 = 0,          i1 = 0;

        int i = lane;
        // unroll x2: 2 independent 16B loads in flight, strict > keeps earliest index
        for (; i + 32 < n4; i += 64) {
            float4 a = s4[i];
            float4 b = s4[i + 32];
            int ba = i << 2;
            int bb = (i + 32) << 2;
            if (a.x > v0) { v0 = a.x; i0 = ba;     }
            if (a.y > v0) { v0 = a.y; i0 = ba + 1; }
            if (a.z > v0) { v0 = a.z; i0 = ba + 2; }
            if (a.w > v0) { v0 = a.w; i0 = ba + 3; }
            if (b.x > v1) { v1 = b.x; i1 = bb;     }
            if (b.y > v1) { v1 = b.y; i1 = bb + 1; }
            if (b.z > v1) { v1 = b.z; i1 = bb + 2; }
            if (b.w > v1) { v1 = b.w; i1 = bb + 3; }
        }
        for (; i < n4; i += 32) {
            float4 a = s4[i];
            int ba = i << 2;
            if (a.x > v0) { v0 = a.x; i0 = ba;     }
            if (a.y > v0) { v0 = a.y; i0 = ba + 1; }
            if (a.z > v0) { v0 = a.z; i0 = ba + 2; }
            if (a.w > v0) { v0 = a.w; i0 = ba + 3; }
        }
        // scalar remainder (none for C=2728; kept for generality)
        for (int c = (n4 << 2) + lane; c < C; c += 32) {
            float a = src[c];
            if (a > v0) { v0 = a; i0 = c; }
        }

        MRG(v0, i0, v1, i1);

        #pragma unroll
        for (int off = 16; off > 0; off >>= 1) {
            float ov = __shfl_down_sync(FULL_MASK, v0, off);
            int   oi = __shfl_down_sync(FULL_MASK, i0, off);
            MRG(v0, i0, ov, oi);
        }
        if (lane == 0) { s_val[warp] = v0; s_idx[warp] = i0; }
    }
    __syncthreads();

    // tail: 4 lanes of warp 0 each finish one row
    if (warp == 0 && lane < 4) {
        const int r = blockIdx.x * 4 + lane;
        if (r < B) {
            const int pred_top = s_idx[lane * 2 + 0];
            const int true_top = s_idx[lane * 2 + 1];
            const float* prow = y_pred + (size_t)r * C;

            const int len_p = path_len[pred_top];
            const int len_t = path_len[true_top];
            const int lmin  = (len_p < len_t) ? len_p : len_t;
            const int diff  = (len_p > len_t) ? (len_p - len_t) : (len_t - len_p);

            float total = 0.0f;
            if (diff != 0) {   // else total is exactly 0
                float local = 0.0f;
                #pragma unroll
                for (int l = 0; l < DLEV; l++) {
                    if (l < lmin) {
                        const int start = sib_start[true_top * DLEV + l];
                        const int size  = sib_size [true_top * DLEV + l];
                        const int tid_l = path_ids [true_top * DLEV + l];

                        // lse of (y_pred * 0/1 mask): masked-out classes contribute exp(0)=1
                        float s = (float)(C - size);
                        for (int c = start; c < start + size; c++) {
                            s += expf(prow[c]);      // L2-hot (row just streamed)
                        }
                        const float lse = logf(s);
                        const float ce  = lse - prow[tid_l];
                        const float h   = (float)(len_t - l - 1);
                        local += expf(-0.5f * h) * ce;
                    }
                }
                total = local * (1.5f * (float)diff) * class_weights[true_top];
            }
            g_row_total[r] = total;
        }
    }
}

__global__ void __launch_bounds__(256)
hier_loss_reduce_kernel(float* __restrict__ out, int B)
{
    __shared__ float s_sum[8];
    const int warp = threadIdx.x >> 5;
    const int lane = threadIdx.x & 31;

    // B/4 float4 values, 256 threads
    const float4* r4 = reinterpret_cast<const float4*>(g_row_total);
    const int n4 = B >> 2;
    float sum = 0.0f;
    for (int i = threadIdx.x; i < n4; i += 256) {
        float4 a = r4[i];
        sum += (a.x + a.y) + (a.z + a.w);
    }
    for (int c = (n4 << 2) + threadIdx.x; c < B; c += 256) sum += g_row_total[c];

    #pragma unroll
    for (int off = 16; off > 0; off >>= 1)
        sum += __shfl_down_sync(FULL_MASK, sum, off);
    if (lane == 0) s_sum[warp] = sum;
    __syncthreads();
    if (warp == 0) {
        float v = (lane < 8) ? s_sum[lane] : 0.0f;
        #pragma unroll
        for (int off = 4; off > 0; off >>= 1)
            v += __shfl_down_sync(FULL_MASK, v, off);
        if (lane == 0) out[0] = v / (float)B;
    }
}

extern "C" void kernel_launch(void* const* d_in, const int* in_sizes, int n_in,
                              void* d_out, int out_size)
{
    const float* y_pred        = (const float*)d_in[0];
    const float* y_true        = (const float*)d_in[1];
    const float* class_weights = (const float*)d_in[2];
    const int*   path_ids      = (const int*)  d_in[3];
    const int*   path_len      = (const int*)  d_in[4];
    const int*   sib_start     = (const int*)  d_in[5];
    const int*   sib_size      = (const int*)  d_in[6];

    const int C = in_sizes[2];            // 2728
    const int B = in_sizes[0] / C;        // 4096

    const int blocks = (B + 3) / 4;       // 4 rows/block, 2 warps per row -> 1024 blocks

    hier_loss_row_kernel<<<blocks, 256>>>(
        y_pred, y_true, class_weights, path_ids, path_len, sib_start, sib_size, B, C);
    hier_loss_reduce_kernel<<<1, 256>>>((float*)d_out, B);
}

// round 6
// speedup vs baseline: 1.3570x; 1.0399x over previous
#include <cuda_runtime.h>
#include <math.h>

#define FULL_MASK 0xffffffffu
#define DLEV 5

// Global accumulator state (device allocation is forbidden).
// Last block resets both after use -> graph-replay safe.
__device__ float        g_acc   = 0.0f;
__device__ unsigned int g_count = 0;

// merge two trackers, lowest index wins ties
#define MRG(V, I, V2, I2)                                 \
    do {                                                  \
        if ((V2) > (V) || ((V2) == (V) && (I2) < (I))) {  \
            (V) = (V2); (I) = (I2);                       \
        }                                                 \
    } while (0)

// 256 threads = 8 warps = 8 rows/block (one warp per row, R1 layout)
__global__ void __launch_bounds__(256)
hier_loss_kernel(
    const float* __restrict__ y_pred,
    const float* __restrict__ y_true,
    const float* __restrict__ class_weights,
    const int*   __restrict__ path_ids,   // [C, D]
    const int*   __restrict__ path_len,   // [C]
    const int*   __restrict__ sib_start,  // [C, D]
    const int*   __restrict__ sib_size,   // [C, D]
    float* __restrict__ out,
    int B, int C)
{
    const int warp = threadIdx.x >> 5;
    const int lane = threadIdx.x & 31;
    const int row  = blockIdx.x * 8 + warp;

    __shared__ float s_part[8];

    float row_total = 0.0f;

    if (row < B) {
        const float* prow = y_pred + (size_t)row * C;
        const float* trow = y_true + (size_t)row * C;

        // ---- fused dual argmax (R1 loop: float4, first-index tiebreak) ----
        float pv = -INFINITY, tv = -INFINITY;
        int   pi = 0,          ti = 0;

        const int n4 = C >> 2;  // 682 for C=2728
        const float4* p4 = reinterpret_cast<const float4*>(prow);
        const float4* t4 = reinterpret_cast<const float4*>(trow);

        for (int i = lane; i < n4; i += 32) {
            float4 a = p4[i];
            float4 b = t4[i];
            int base = i << 2;
            if (a.x > pv) { pv = a.x; pi = base;     }
            if (a.y > pv) { pv = a.y; pi = base + 1; }
            if (a.z > pv) { pv = a.z; pi = base + 2; }
            if (a.w > pv) { pv = a.w; pi = base + 3; }
            if (b.x > tv) { tv = b.x; ti = base;     }
            if (b.y > tv) { tv = b.y; ti = base + 1; }
            if (b.z > tv) { tv = b.z; ti = base + 2; }
            if (b.w > tv) { tv = b.w; ti = base + 3; }
        }
        for (int c = (n4 << 2) + lane; c < C; c += 32) {
            float a = prow[c];
            float b = trow[c];
            if (a > pv) { pv = a; pi = c; }
            if (b > tv) { tv = b; ti = c; }
        }

        #pragma unroll
        for (int off = 16; off > 0; off >>= 1) {
            float opv = __shfl_down_sync(FULL_MASK, pv, off);
            int   opi = __shfl_down_sync(FULL_MASK, pi, off);
            MRG(pv, pi, opv, opi);
            float otv = __shfl_down_sync(FULL_MASK, tv, off);
            int   oti = __shfl_down_sync(FULL_MASK, ti, off);
            MRG(tv, ti, otv, oti);
        }

        if (lane == 0) {
            const int pred_top = pi;
            const int true_top = ti;
            const int len_p = path_len[pred_top];
            const int len_t = path_len[true_top];
            const int lmin  = (len_p < len_t) ? len_p : len_t;
            const int diff  = (len_p > len_t) ? (len_p - len_t) : (len_t - len_p);

            if (diff != 0) {   // else row_total is exactly 0
                float local = 0.0f;
                #pragma unroll
                for (int l = 0; l < DLEV; l++) {
                    if (l < lmin) {
                        const int start = sib_start[true_top * DLEV + l];
                        const int size  = sib_size [true_top * DLEV + l];
                        const int tid_l = path_ids [true_top * DLEV + l];

                        // lse of (y_pred * 0/1 mask): masked-out classes contribute exp(0)=1
                        float s = (float)(C - size);
                        for (int c = start; c < start + size; c++) {
                            s += expf(prow[c]);      // L2-hot (row just streamed)
                        }
                        const float lse = logf(s);
                        const float ce  = lse - prow[tid_l];
                        const float h   = (float)(len_t - l - 1);
                        local += expf(-0.5f * h) * ce;
                    }
                }
                row_total = local * (1.5f * (float)diff) * class_weights[true_top];
            }
        }
    }

    // ---- block partial sum (8 values) -> one float atomicAdd ----
    if (lane == 0) s_part[warp] = row_total;
    __syncthreads();

    __shared__ bool s_is_last;
    if (threadIdx.x == 0) {
        float part = 0.0f;
        #pragma unroll
        for (int w = 0; w < 8; w++) part += s_part[w];
        atomicAdd(&g_acc, part);
        __threadfence();                          // order value-add before counter-add
        unsigned int done = atomicAdd(&g_count, 1u);
        s_is_last = (done == gridDim.x - 1);
    }
    __syncthreads();

    // ---- last block: O(1) finalize + reset for next graph replay ----
    if (s_is_last && threadIdx.x == 0) {
        __threadfence();                          // acquire
        float total = atomicAdd(&g_acc, 0.0f);    // atomic read at L2
        out[0] = total / (float)B;
        g_acc   = 0.0f;
        g_count = 0;
    }
}

extern "C" void kernel_launch(void* const* d_in, const int* in_sizes, int n_in,
                              void* d_out, int out_size)
{
    const float* y_pred        = (const float*)d_in[0];
    const float* y_true        = (const float*)d_in[1];
    const float* class_weights = (const float*)d_in[2];
    const int*   path_ids      = (const int*)  d_in[3];
    const int*   path_len      = (const int*)  d_in[4];
    const int*   sib_start     = (const int*)  d_in[5];
    const int*   sib_size      = (const int*)  d_in[6];

    const int C = in_sizes[2];            // 2728
    const int B = in_sizes[0] / C;        // 4096

    const int blocks = (B + 7) / 8;       // 512: 8 rows/block, one warp per row

    hier_loss_kernel<<<blocks, 256>>>(
        y_pred, y_true, class_weights, path_ids, path_len, sib_start, sib_size,
        (float*)d_out, B, C);
}

// round 7
// speedup vs baseline: 1.4774x; 1.0887x over previous
#include <cuda_runtime.h>
#include <math.h>

#define FULL_MASK 0xffffffffu
#define DLEV 5

// Global accumulator state (device allocation is forbidden).
// Last block resets both after use -> graph-replay safe.
__device__ float        g_acc   = 0.0f;
__device__ unsigned int g_count = 0;

__device__ __forceinline__ float max4(float4 q) {
    return fmaxf(fmaxf(q.x, q.y), fmaxf(q.z, q.w));
}

// first element of q equal to m -> global index (slot*4 + j)
__device__ __forceinline__ int first_eq_idx(float4 q, float m, int slot) {
    int j;
    if      (q.x == m) j = 0;
    else if (q.y == m) j = 1;
    else if (q.z == m) j = 2;
    else               j = 3;
    return (slot << 2) + j;
}

// 256 threads = 8 warps = 8 rows/block (one warp per row)
__global__ void __launch_bounds__(256)
hier_loss_kernel(
    const float* __restrict__ y_pred,
    const float* __restrict__ y_true,
    const float* __restrict__ class_weights,
    const int*   __restrict__ path_ids,   // [C, D]
    const int*   __restrict__ path_len,   // [C]
    const int*   __restrict__ sib_start,  // [C, D]
    const int*   __restrict__ sib_size,   // [C, D]
    float* __restrict__ out,
    int B, int C)
{
    const int warp = threadIdx.x >> 5;
    const int lane = threadIdx.x & 31;
    const int row  = blockIdx.x * 8 + warp;

    __shared__ float s_part[8];

    float row_total = 0.0f;

    if (row < B) {
        const float* prow = y_pred + (size_t)row * C;
        const float* trow = y_true + (size_t)row * C;
        const int n4 = C >> 2;  // 682 for C=2728
        const float4* p4 = reinterpret_cast<const float4*>(prow);
        const float4* t4 = reinterpret_cast<const float4*>(trow);

        // ---- pass 1: values-only max, remember winning float4 slot ----
        // two trackers per tensor (slot1 > slot0 always, so strict > keeps earliest)
        float pv0 = -INFINITY, pv1 = -INFINITY, tv0 = -INFINITY, tv1 = -INFINITY;
        int   ps0 = 0, ps1 = 0, ts0 = 0, ts1 = 0;

        int i = lane;
        for (; i + 32 < n4; i += 64) {
            float4 a0 = p4[i];
            float4 a1 = p4[i + 32];
            float4 b0 = t4[i];
            float4 b1 = t4[i + 32];
            float ma0 = max4(a0), ma1 = max4(a1);
            float mb0 = max4(b0), mb1 = max4(b1);
            if (ma0 > pv0) { pv0 = ma0; ps0 = i;      }
            if (ma1 > pv1) { pv1 = ma1; ps1 = i + 32; }
            if (mb0 > tv0) { tv0 = mb0; ts0 = i;      }
            if (mb1 > tv1) { tv1 = mb1; ts1 = i + 32; }
        }
        for (; i < n4; i += 32) {
            float4 a = p4[i];
            float4 b = t4[i];
            float ma = max4(a), mb = max4(b);
            if (ma > pv0) { pv0 = ma; ps0 = i; }
            if (mb > tv0) { tv0 = mb; ts0 = i; }
        }
        // merge trackers (tracker1 slots are always later -> strict > keeps earliest)
        if (pv1 > pv0) { pv0 = pv1; ps0 = ps1; }
        if (tv1 > tv0) { tv0 = tv1; ts0 = ts1; }

        // scalar remainder with exact indices (none for C=2728; kept for generality)
        float prv = -INFINITY, trv = -INFINITY;
        int   pri = 0x7FFFFFFF, tri = 0x7FFFFFFF;
        for (int c = (n4 << 2) + lane; c < C; c += 32) {
            float a = prow[c];
            float b = trow[c];
            if (a > prv) { prv = a; pri = c; }
            if (b > trv) { trv = b; tri = c; }
        }

        // ---- warp max of values (broadcast to all lanes) ----
        float wp = fmaxf(pv0, prv);
        float wt = fmaxf(tv0, trv);
        #pragma unroll
        for (int off = 16; off > 0; off >>= 1) {
            wp = fmaxf(wp, __shfl_xor_sync(FULL_MASK, wp, off));
            wt = fmaxf(wt, __shfl_xor_sync(FULL_MASK, wt, off));
        }

        // ---- pass 2: lanes holding the max reload one float4 (L1-hit) ----
        int pcand = 0x7FFFFFFF;
        if (pv0 == wp) pcand = first_eq_idx(p4[ps0], wp, ps0);
        if (prv == wp) pcand = min(pcand, pri);
        int tcand = 0x7FFFFFFF;
        if (tv0 == wt) tcand = first_eq_idx(t4[ts0], wt, ts0);
        if (trv == wt) tcand = min(tcand, tri);
        #pragma unroll
        for (int off = 16; off > 0; off >>= 1) {
            pcand = min(pcand, __shfl_xor_sync(FULL_MASK, pcand, off));
            tcand = min(tcand, __shfl_xor_sync(FULL_MASK, tcand, off));
        }

        if (lane == 0) {
            const int pred_top = pcand;
            const int true_top = tcand;
            const int len_p = path_len[pred_top];
            const int len_t = path_len[true_top];
            const int lmin  = (len_p < len_t) ? len_p : len_t;
            const int diff  = (len_p > len_t) ? (len_p - len_t) : (len_t - len_p);

            if (diff != 0) {   // else row_total is exactly 0
                float local = 0.0f;
                #pragma unroll
                for (int l = 0; l < DLEV; l++) {
                    if (l < lmin) {
                        const int start = sib_start[true_top * DLEV + l];
                        const int size  = sib_size [true_top * DLEV + l];
                        const int tid_l = path_ids [true_top * DLEV + l];

                        // lse of (y_pred * 0/1 mask): masked-out classes contribute exp(0)=1
                        float s = (float)(C - size);
                        for (int c = start; c < start + size; c++) {
                            s += expf(prow[c]);      // L2-hot (row just streamed)
                        }
                        const float lse = logf(s);
                        const float ce  = lse - prow[tid_l];
                        const float h   = (float)(len_t - l - 1);
                        local += expf(-0.5f * h) * ce;
                    }
                }
                row_total = local * (1.5f * (float)diff) * class_weights[true_top];
            }
        }
    }

    // ---- block partial sum (8 values) -> one float atomicAdd ----
    if (lane == 0) s_part[warp] = row_total;
    __syncthreads();

    __shared__ bool s_is_last;
    if (threadIdx.x == 0) {
        float part = 0.0f;
        #pragma unroll
        for (int w = 0; w < 8; w++) part += s_part[w];
        atomicAdd(&g_acc, part);
        __threadfence();                          // order value-add before counter-add
        unsigned int done = atomicAdd(&g_count, 1u);
        s_is_last = (done == gridDim.x - 1);
    }
    __syncthreads();

    // ---- last block: O(1) finalize + reset for next graph replay ----
    if (s_is_last && threadIdx.x == 0) {
        __threadfence();                          // acquire
        float total = atomicAdd(&g_acc, 0.0f);    // atomic read at L2
        out[0] = total / (float)B;
        g_acc   = 0.0f;
        g_count = 0;
    }
}

extern "C" void kernel_launch(void* const* d_in, const int* in_sizes, int n_in,
                              void* d_out, int out_size)
{
    const float* y_pred        = (const float*)d_in[0];
    const float* y_true        = (const float*)d_in[1];
    const float* class_weights = (const float*)d_in[2];
    const int*   path_ids      = (const int*)  d_in[3];
    const int*   path_len      = (const int*)  d_in[4];
    const int*   sib_start     = (const int*)  d_in[5];
    const int*   sib_size      = (const int*)  d_in[6];

    const int C = in_sizes[2];            // 2728
    const int B = in_sizes[0] / C;        // 4096

    const int blocks = (B + 7) / 8;       // 512: 8 rows/block, one warp per row

    hier_loss_kernel<<<blocks, 256>>>(
        y_pred, y_true, class_weights, path_ids, path_len, sib_start, sib_size,
        (float*)d_out, B, C);
}